// round 1
// baseline (speedup 1.0000x reference)
#include <cuda_runtime.h>
#include <cstdint>
#include <cstddef>

#define DEV __device__ __forceinline__

constexpr int kA = 8;
constexpr int kD = 128;
constexpr int kH = 64;
constexpr int kG = 192;   // 3*H
constexpr int kQ = 16;
constexpr int BB = 128;   // batch rows per CTA
constexpr int NTHREADS = 512;

// ---- shared memory layout (in floats) ----
// Strides chosen ≡ 4 (mod 32) so row-strided accesses hit distinct banks.
constexpr int XS_STRIDE = 132;                  // X tile [BB][132]  (lives in [0, 16896))
constexpr int ZS = 68;                          // stride for z1 / h / hnew tiles
constexpr int OFF_Z1  = 0;                      // z1   [BB][68]  (after X is dead)
constexpr int OFF_HN  = BB * ZS;                // 8704  hnew [BB][68]
constexpr int OFF_W   = 2 * BB * ZS;            // 17408 weights region
constexpr int WST     = 196;                    // stride of transposed gate weights
constexpr int OFF_WHH = OFF_W + kH * WST;       // 29952
constexpr int OFF_H   = OFF_W + 2 * kH * WST;   // 42496 h_in [BB][68]
constexpr int OFF_B   = OFF_H + BB * ZS;        // 51200 biases
constexpr int OFF_B1  = OFF_B;                  // 64
constexpr int OFF_BIH = OFF_B + 64;             // 192
constexpr int OFF_BHH = OFF_B + 256;            // 192
constexpr int OFF_B2  = OFF_B + 448;            // 16
constexpr int SMEM_FLOATS = OFF_B + 464;        // 51664 floats = 206656 B

// ---- packed f32x2 helpers (ptxas will NOT auto-fuse; must be inline PTX) ----
DEV unsigned long long fma2(unsigned long long a, unsigned long long b,
                            unsigned long long c) {
  unsigned long long d;
  asm("fma.rn.f32x2 %0, %1, %2, %3;" : "=l"(d) : "l"(a), "l"(b), "l"(c));
  return d;
}
DEV unsigned long long dup2(float x) {
  unsigned long long r;
  asm("mov.b64 %0, {%1, %1};" : "=l"(r) : "f"(x));
  return r;
}
DEV void upk2(unsigned long long v, float& x, float& y) {
  asm("mov.b64 {%0, %1}, %2;" : "=f"(x), "=f"(y) : "l"(v));
}

DEV float sigmoidf_(float x) {
  float e = __expf(-x);
  return __fdividef(1.0f, 1.0f + e);
}
DEV float tanhf_(float x) {
  float e = __expf(2.0f * x);
  return 1.0f - __fdividef(2.0f, e + 1.0f);
}

__global__ void __launch_bounds__(NTHREADS, 1)
rnn_fused_kernel(const float* __restrict__ inputs,
                 const float* __restrict__ hidden,
                 const float* __restrict__ W1,  const float* __restrict__ b1,
                 const float* __restrict__ Wih, const float* __restrict__ bih,
                 const float* __restrict__ Whh, const float* __restrict__ bhh,
                 const float* __restrict__ W2,  const float* __restrict__ b2,
                 float* __restrict__ out_q, float* __restrict__ out_h)
{
  extern __shared__ float smf[];
  const int a  = blockIdx.y;
  const int b0 = blockIdx.x * BB;
  const int tid = threadIdx.x;
  const int tx = tid & 15;          // 16 column-groups of 4 -> 64 cols
  const int ty = tid >> 4;          // 32 row-groups of 4   -> 128 rows
  const int r0 = ty * 4;
  const int c0 = tx * 4;

  // ============ cooperative loads: X, W1^T, H_in, biases ============
  {
    const float* xg = inputs + ((size_t)b0 * kA + a) * kD;
    #pragma unroll 4
    for (int idx = tid; idx < BB * (kD / 4); idx += NTHREADS) {
      int row = idx >> 5, c4 = (idx & 31) << 2;
      float4 v = *reinterpret_cast<const float4*>(xg + (size_t)row * (kA * kD) + c4);
      *reinterpret_cast<float4*>(&smf[row * XS_STRIDE + c4]) = v;
    }
    const float* w1g = W1 + (size_t)a * kH * kD;
    #pragma unroll 4
    for (int idx = tid; idx < kH * kD; idx += NTHREADS) {
      int h = idx >> 7, d = idx & 127;
      smf[OFF_W + d * ZS + h] = w1g[idx];          // W1t[d][h], stride 68
    }
    const float* hg = hidden + ((size_t)b0 * kA + a) * kH;
    #pragma unroll 4
    for (int idx = tid; idx < BB * (kH / 4); idx += NTHREADS) {
      int row = idx >> 4, c4 = (idx & 15) << 2;
      float4 v = *reinterpret_cast<const float4*>(hg + (size_t)row * (kA * kH) + c4);
      *reinterpret_cast<float4*>(&smf[OFF_H + row * ZS + c4]) = v;
    }
    if (tid < 64)        smf[OFF_B1  + tid      ] = b1 [a * kH + tid];
    else if (tid < 256)  smf[OFF_BIH + tid -  64] = bih[a * kG + tid -  64];
    else if (tid < 448)  smf[OFF_BHH + tid - 256] = bhh[a * kG + tid - 256];
    else if (tid < 464)  smf[OFF_B2  + tid - 448] = b2 [a * kQ + tid - 448];
  }
  __syncthreads();

  // ============ stage 1: z1 = relu(X @ W1^T + b1) ============
  unsigned long long z1acc[4][2];
  #pragma unroll
  for (int i = 0; i < 4; ++i) { z1acc[i][0] = 0ull; z1acc[i][1] = 0ull; }

  #pragma unroll 2
  for (int k4 = 0; k4 < kD / 4; ++k4) {
    float4 xr[4];
    #pragma unroll
    for (int i = 0; i < 4; ++i)
      xr[i] = *reinterpret_cast<const float4*>(&smf[(r0 + i) * XS_STRIDE + k4 * 4]);
    #pragma unroll
    for (int kk = 0; kk < 4; ++kk) {
      const float* wrow = &smf[OFF_W + (k4 * 4 + kk) * ZS + c0];
      unsigned long long w01 = *reinterpret_cast<const unsigned long long*>(wrow);
      unsigned long long w23 = *reinterpret_cast<const unsigned long long*>(wrow + 2);
      #pragma unroll
      for (int i = 0; i < 4; ++i) {
        float xv = reinterpret_cast<const float*>(&xr[i])[kk];
        unsigned long long xx = dup2(xv);
        z1acc[i][0] = fma2(w01, xx, z1acc[i][0]);
        z1acc[i][1] = fma2(w23, xx, z1acc[i][1]);
      }
    }
  }
  __syncthreads();   // all X / W1t reads done; regions may be reused now

  {
    float bx = smf[OFF_B1 + c0 + 0], by = smf[OFF_B1 + c0 + 1];
    float bz = smf[OFF_B1 + c0 + 2], bw = smf[OFF_B1 + c0 + 3];
    #pragma unroll
    for (int i = 0; i < 4; ++i) {
      float v0, v1, v2, v3;
      upk2(z1acc[i][0], v0, v1);
      upk2(z1acc[i][1], v2, v3);
      float4 z;
      z.x = fmaxf(v0 + bx, 0.f); z.y = fmaxf(v1 + by, 0.f);
      z.z = fmaxf(v2 + bz, 0.f); z.w = fmaxf(v3 + bw, 0.f);
      *reinterpret_cast<float4*>(&smf[OFF_Z1 + (r0 + i) * ZS + c0]) = z;
    }
  }

  // load gate weights transposed: Wih_t[k][g], Whh_t[k][g] (stride 196)
  {
    const float* wg  = Wih + (size_t)a * kG * kH;
    const float* wg2 = Whh + (size_t)a * kG * kH;
    #pragma unroll 4
    for (int idx = tid; idx < kG * kH; idx += NTHREADS) {
      int g = idx >> 6, k = idx & 63;
      smf[OFF_W   + k * WST + g] = wg [idx];
      smf[OFF_WHH + k * WST + g] = wg2[idx];
    }
  }
  __syncthreads();

  // ============ stage 2: gate GEMMs ============
  unsigned long long ar[4][2], az[4][2], an[4][2], ah[4][2];
  #pragma unroll
  for (int i = 0; i < 4; ++i) {
    ar[i][0] = ar[i][1] = 0ull;
    az[i][0] = az[i][1] = 0ull;
    an[i][0] = an[i][1] = 0ull;
    ah[i][0] = ah[i][1] = 0ull;
  }

  #pragma unroll 2
  for (int k2 = 0; k2 < kH / 2; ++k2) {
    const int k = k2 * 2;
    float2 zf[4], hf[4];
    #pragma unroll
    for (int i = 0; i < 4; ++i) {
      zf[i] = *reinterpret_cast<const float2*>(&smf[OFF_Z1 + (r0 + i) * ZS + k]);
      hf[i] = *reinterpret_cast<const float2*>(&smf[OFF_H  + (r0 + i) * ZS + k]);
    }
    #pragma unroll
    for (int kk = 0; kk < 2; ++kk) {
      const float* wi = &smf[OFF_W   + (k + kk) * WST];
      const float* wh = &smf[OFF_WHH + (k + kk) * WST];
      unsigned long long wri0 = *reinterpret_cast<const unsigned long long*>(wi + c0);
      unsigned long long wri1 = *reinterpret_cast<const unsigned long long*>(wi + c0 + 2);
      unsigned long long wzi0 = *reinterpret_cast<const unsigned long long*>(wi + 64 + c0);
      unsigned long long wzi1 = *reinterpret_cast<const unsigned long long*>(wi + 64 + c0 + 2);
      unsigned long long wni0 = *reinterpret_cast<const unsigned long long*>(wi + 128 + c0);
      unsigned long long wni1 = *reinterpret_cast<const unsigned long long*>(wi + 128 + c0 + 2);
      unsigned long long wrh0 = *reinterpret_cast<const unsigned long long*>(wh + c0);
      unsigned long long wrh1 = *reinterpret_cast<const unsigned long long*>(wh + c0 + 2);
      unsigned long long wzh0 = *reinterpret_cast<const unsigned long long*>(wh + 64 + c0);
      unsigned long long wzh1 = *reinterpret_cast<const unsigned long long*>(wh + 64 + c0 + 2);
      unsigned long long wnh0 = *reinterpret_cast<const unsigned long long*>(wh + 128 + c0);
      unsigned long long wnh1 = *reinterpret_cast<const unsigned long long*>(wh + 128 + c0 + 2);
      #pragma unroll
      for (int i = 0; i < 4; ++i) {
        float zv = kk ? zf[i].y : zf[i].x;
        float hv = kk ? hf[i].y : hf[i].x;
        unsigned long long zz = dup2(zv);
        unsigned long long hh = dup2(hv);
        ar[i][0] = fma2(wri0, zz, ar[i][0]); ar[i][0] = fma2(wrh0, hh, ar[i][0]);
        ar[i][1] = fma2(wri1, zz, ar[i][1]); ar[i][1] = fma2(wrh1, hh, ar[i][1]);
        az[i][0] = fma2(wzi0, zz, az[i][0]); az[i][0] = fma2(wzh0, hh, az[i][0]);
        az[i][1] = fma2(wzi1, zz, az[i][1]); az[i][1] = fma2(wzh1, hh, az[i][1]);
        an[i][0] = fma2(wni0, zz, an[i][0]);
        an[i][1] = fma2(wni1, zz, an[i][1]);
        ah[i][0] = fma2(wnh0, hh, ah[i][0]);
        ah[i][1] = fma2(wnh1, hh, ah[i][1]);
      }
    }
  }

  // ============ stage 3: GRU gates + h_new ============
  {
    float bir[4], biz[4], bin[4], bhr[4], bhz[4], bhn[4];
    #pragma unroll
    for (int j = 0; j < 4; ++j) {
      bir[j] = smf[OFF_BIH +       c0 + j];
      biz[j] = smf[OFF_BIH +  64 + c0 + j];
      bin[j] = smf[OFF_BIH + 128 + c0 + j];
      bhr[j] = smf[OFF_BHH +       c0 + j];
      bhz[j] = smf[OFF_BHH +  64 + c0 + j];
      bhn[j] = smf[OFF_BHH + 128 + c0 + j];
    }
    #pragma unroll
    for (int i = 0; i < 4; ++i) {
      float arf[4], azf[4], anf[4], ahf[4];
      upk2(ar[i][0], arf[0], arf[1]); upk2(ar[i][1], arf[2], arf[3]);
      upk2(az[i][0], azf[0], azf[1]); upk2(az[i][1], azf[2], azf[3]);
      upk2(an[i][0], anf[0], anf[1]); upk2(an[i][1], anf[2], anf[3]);
      upk2(ah[i][0], ahf[0], ahf[1]); upk2(ah[i][1], ahf[2], ahf[3]);
      const float4 hold = *reinterpret_cast<const float4*>(&smf[OFF_H + (r0 + i) * ZS + c0]);
      const float ho[4] = {hold.x, hold.y, hold.z, hold.w};
      float hn[4];
      #pragma unroll
      for (int j = 0; j < 4; ++j) {
        float R  = sigmoidf_(arf[j] + bir[j] + bhr[j]);
        float Zg = sigmoidf_(azf[j] + biz[j] + bhz[j]);
        float n  = tanhf_(anf[j] + bin[j] + R * (ahf[j] + bhn[j]));
        hn[j] = n + Zg * (ho[j] - n);          // (1-z)*n + z*h
      }
      float4 hv4 = make_float4(hn[0], hn[1], hn[2], hn[3]);
      *reinterpret_cast<float4*>(&smf[OFF_HN + (r0 + i) * ZS + c0]) = hv4;
      *reinterpret_cast<float4*>(&out_h[((size_t)(b0 + r0 + i) * kA + a) * kH + c0]) = hv4;
    }
  }
  __syncthreads();   // stage-2 weight reads done; HN tile complete

  // ============ stage 4: q = h_new @ W2^T + b2 ============
  {
    const float* w2g = W2 + (size_t)a * kQ * kH;
    for (int idx = tid; idx < kQ * kH; idx += NTHREADS) {
      int n = idx >> 6, k = idx & 63;
      smf[OFF_W + k * kQ + n] = w2g[idx];      // W2t[k][n]
    }
  }
  __syncthreads();
  {
    const int qc  = tid & 15;
    const int qr0 = (tid >> 4) * 4;
    float qa0 = 0.f, qa1 = 0.f, qa2 = 0.f, qa3 = 0.f;
    #pragma unroll 8
    for (int k = 0; k < kH; ++k) {
      float w = smf[OFF_W + k * kQ + qc];
      qa0 = fmaf(smf[OFF_HN + (qr0 + 0) * ZS + k], w, qa0);
      qa1 = fmaf(smf[OFF_HN + (qr0 + 1) * ZS + k], w, qa1);
      qa2 = fmaf(smf[OFF_HN + (qr0 + 2) * ZS + k], w, qa2);
      qa3 = fmaf(smf[OFF_HN + (qr0 + 3) * ZS + k], w, qa3);
    }
    float bq = smf[OFF_B2 + qc];
    out_q[((size_t)(b0 + qr0 + 0) * kA + a) * kQ + qc] = qa0 + bq;
    out_q[((size_t)(b0 + qr0 + 1) * kA + a) * kQ + qc] = qa1 + bq;
    out_q[((size_t)(b0 + qr0 + 2) * kA + a) * kQ + qc] = qa2 + bq;
    out_q[((size_t)(b0 + qr0 + 3) * kA + a) * kQ + qc] = qa3 + bq;
  }
}

extern "C" void kernel_launch(void* const* d_in, const int* in_sizes, int n_in,
                              void* d_out, int out_size) {
  (void)n_in; (void)out_size;
  const float* inputs = (const float*)d_in[0];
  const float* hidden = (const float*)d_in[1];
  const float* W1  = (const float*)d_in[2];
  const float* b1  = (const float*)d_in[3];
  const float* Wih = (const float*)d_in[4];
  const float* bih = (const float*)d_in[5];
  const float* Whh = (const float*)d_in[6];
  const float* bhh = (const float*)d_in[7];
  const float* W2  = (const float*)d_in[8];
  const float* b2  = (const float*)d_in[9];

  const int B = in_sizes[0] / (kA * kD);   // 16384
  float* out_q = (float*)d_out;
  float* out_h = out_q + (size_t)B * kA * kQ;

  const size_t smem = (size_t)SMEM_FLOATS * sizeof(float);  // 206656 B
  cudaFuncSetAttribute(rnn_fused_kernel,
                       cudaFuncAttributeMaxDynamicSharedMemorySize, (int)smem);
  dim3 grid(B / BB, kA, 1);
  rnn_fused_kernel<<<grid, NTHREADS, smem>>>(inputs, hidden, W1, b1, Wih, bih,
                                             Whh, bhh, W2, b2, out_q, out_h);
}